// round 14
// baseline (speedup 1.0000x reference)
#include <cuda_runtime.h>
#include <cuda_bf16.h>
#include <cuda_fp16.h>
#include <cstdint>

#define PB    2
#define PT    10000
#define PM    100000
#define PD    128
#define PDOUT 128
#define NROWS (PB * PT * 2)   // 40000

#define WPAD 136              // padded row length (bf16) -> 272 B rows, conflict-free ldmatrix

// ---------------------------------------------------------------------------
// Device scratch (no allocation allowed; zero-initialized at module load)
// ---------------------------------------------------------------------------
__device__ float  g_y [NROWS * PDOUT];                       // bias-free x@W^T (f32)
__device__ __align__(16) __half g_yh[NROWS * PDOUT];         // fp16 copy for gathers
__device__ __align__(16) __nv_bfloat16 g_Whi[PDOUT * WPAD];
__device__ __align__(16) __nv_bfloat16 g_Wlo[PDOUT * WPAD];
__device__ int g_counts[PT];        // zeroed at load; re-zeroed by scanfill each run
__device__ int g_offsets[PT + 1];
__device__ int g_cursor[PT];
__device__ __align__(16) float4 g_edata[PM];   // {bits(node_out), w_b0, w_b1, 0}
__device__ int g_bagg[128];
__device__ unsigned g_bar;          // grid-barrier counter, reset by prep each replay

// ---------------------------------------------------------------------------
// Warp MMA helpers (sm_80-baseline; valid in family-generic compute_103 PTX)
// ---------------------------------------------------------------------------
__device__ __forceinline__ uint32_t smem_u32(const void* p) {
    uint32_t a;
    asm("{ .reg .u64 t; cvta.to.shared.u64 t, %1; cvt.u32.u64 %0, t; }" : "=r"(a) : "l"(p));
    return a;
}
__device__ __forceinline__ void ldsm_x4(uint32_t* r, uint32_t addr) {
    asm volatile("ldmatrix.sync.aligned.m8n8.x4.shared.b16 {%0,%1,%2,%3}, [%4];"
                 : "=r"(r[0]), "=r"(r[1]), "=r"(r[2]), "=r"(r[3]) : "r"(addr));
}
__device__ __forceinline__ void ldsm_x2(uint32_t* r, uint32_t addr) {
    asm volatile("ldmatrix.sync.aligned.m8n8.x2.shared.b16 {%0,%1}, [%2];"
                 : "=r"(r[0]), "=r"(r[1]) : "r"(addr));
}
__device__ __forceinline__ void mma_bf16(float* c, const uint32_t* a, const uint32_t* b) {
    asm volatile("mma.sync.aligned.m16n8k16.row.col.f32.bf16.bf16.f32 "
                 "{%0,%1,%2,%3}, {%4,%5,%6,%7}, {%8,%9}, {%0,%1,%2,%3};"
                 : "+f"(c[0]), "+f"(c[1]), "+f"(c[2]), "+f"(c[3])
                 : "r"(a[0]), "r"(a[1]), "r"(a[2]), "r"(a[3]), "r"(b[0]), "r"(b[1]));
}
// Load 4 consecutive halfs -> float4 (8 B load)
__device__ __forceinline__ float4 ld_half4(const __half* p) {
    const uint2 u = *(const uint2*)p;
    const float2 f0 = __half22float2(*(const __half2*)&u.x);
    const float2 f1 = __half22float2(*(const __half2*)&u.y);
    return make_float4(f0.x, f0.y, f1.x, f1.y);
}

// ---------------------------------------------------------------------------
// Prep (fused): blocks 0..63 split W into bf16 hi/lo images;
// blocks 64.. histogram node_in. Resets the grid-barrier counter.
// ---------------------------------------------------------------------------
__global__ __launch_bounds__(256) void prep_kernel(
    const float* __restrict__ W, const int* __restrict__ edge)
{
    const int bid = blockIdx.x, tid = threadIdx.x;
    if (bid == 0 && tid == 0) g_bar = 0u;
    if (bid < 64) {
        int idx = bid * 256 + tid;                 // < 16384
        int o = idx >> 7, d = idx & 127;
        float w = W[idx];
        __nv_bfloat16 hi = __float2bfloat16(w);
        __nv_bfloat16 lo = __float2bfloat16(w - __bfloat162float(hi));
        g_Whi[o * WPAD + d] = hi;
        g_Wlo[o * WPAD + d] = lo;
    } else {
        int m = (bid - 64) * 256 + tid;
        if (m < PM) atomicAdd(&g_counts[edge[m]], 1);
    }
}

// ---------------------------------------------------------------------------
// GEMM: y = x @ W^T via mma.sync bf16 split (hi*hi + hi*lo + lo*hi).
// Epilogue writes f32 y AND fp16 yh (gather source).
// ---------------------------------------------------------------------------
#define SM_XHI 0
#define SM_XLO 34816          // 128*272
#define SM_WHI 69632
#define SM_WLO 104448
#define GEMM_SMEM 139264

__global__ __launch_bounds__(256, 1) void mma_gemm_kernel(
    const float* __restrict__ x, float* __restrict__ y, __half* __restrict__ yh)
{
    extern __shared__ char smem[];
    const uint32_t sb = smem_u32(smem);
    const int tid = threadIdx.x, wid = tid >> 5, lane = tid & 31;
    const int row0 = blockIdx.x * 128;

    {
        const uint4* shi = (const uint4*)g_Whi;
        const uint4* slo = (const uint4*)g_Wlo;
        uint4* dhi = (uint4*)(smem + SM_WHI);
        uint4* dlo = (uint4*)(smem + SM_WLO);
#pragma unroll
        for (int i = tid; i < 2176; i += 256) { dhi[i] = shi[i]; dlo[i] = slo[i]; }
    }
    {
#pragma unroll
        for (int i = 0; i < 16; i++) {
            const int idx = i * 256 + tid;
            const int r = idx >> 5, q = idx & 31;
            const int grow = row0 + r;
            float4 v = make_float4(0.f, 0.f, 0.f, 0.f);
            if (grow < NROWS) v = *(const float4*)(x + (size_t)grow * PD + q * 4);

            __nv_bfloat162 h01 = __float22bfloat162_rn(make_float2(v.x, v.y));
            __nv_bfloat162 h23 = __float22bfloat162_rn(make_float2(v.z, v.w));
            float2 f01 = __bfloat1622float2(h01);
            float2 f23 = __bfloat1622float2(h23);
            __nv_bfloat162 l01 = __float22bfloat162_rn(make_float2(v.x - f01.x, v.y - f01.y));
            __nv_bfloat162 l23 = __float22bfloat162_rn(make_float2(v.z - f23.x, v.w - f23.y));

            const int boff = r * 272 + q * 8;
            *(uint2*)(smem + SM_XHI + boff) = make_uint2(*(uint32_t*)&h01, *(uint32_t*)&h23);
            *(uint2*)(smem + SM_XLO + boff) = make_uint2(*(uint32_t*)&l01, *(uint32_t*)&l23);
        }
    }
    __syncthreads();

    const int wm = wid & 1, wn = wid >> 1;
    const int m_base = wm * 64, n_base = wn * 32;

    float acc[4][4][4];
#pragma unroll
    for (int mt = 0; mt < 4; mt++)
#pragma unroll
        for (int nt = 0; nt < 4; nt++)
#pragma unroll
            for (int j = 0; j < 4; j++) acc[mt][nt][j] = 0.f;

    const int g  = lane >> 3;
    const int lr = lane & 7;

#pragma unroll
    for (int ks = 0; ks < 8; ks++) {
        const int k0 = ks * 16;
        uint32_t bh[4][2], bl[4][2];
#pragma unroll
        for (int nt = 0; nt < 4; nt++) {
            const int nrow = n_base + nt * 8 + lr;
            const int ncol = k0 + ((lane >> 3) & 1) * 8;
            const uint32_t off = (uint32_t)(nrow * 272 + ncol * 2);
            ldsm_x2(bh[nt], sb + SM_WHI + off);
            ldsm_x2(bl[nt], sb + SM_WLO + off);
        }
#pragma unroll
        for (int mt = 0; mt < 4; mt++) {
            const int arow = m_base + mt * 16 + (g & 1) * 8 + lr;
            const int acol = k0 + (g >> 1) * 8;
            const uint32_t off = (uint32_t)(arow * 272 + acol * 2);
            uint32_t ah[4], al[4];
            ldsm_x4(ah, sb + SM_XHI + off);
            ldsm_x4(al, sb + SM_XLO + off);
#pragma unroll
            for (int nt = 0; nt < 4; nt++) {
                mma_bf16(acc[mt][nt], ah, bh[nt]);
                mma_bf16(acc[mt][nt], ah, bl[nt]);
                mma_bf16(acc[mt][nt], al, bh[nt]);
            }
        }
    }

    const int erow = m_base + (lane >> 2);
    const int ecol = (lane & 3) * 2;
#pragma unroll
    for (int mt = 0; mt < 4; mt++) {
        const int r0 = row0 + erow + mt * 16;
#pragma unroll
        for (int nt = 0; nt < 4; nt++) {
            const int col = n_base + nt * 8 + ecol;
            if (r0 < NROWS) {
                *(float2*)(y + (size_t)r0 * PDOUT + col) =
                    make_float2(acc[mt][nt][0], acc[mt][nt][1]);
                *(__half2*)(yh + (size_t)r0 * PDOUT + col) =
                    __floats2half2_rn(acc[mt][nt][0], acc[mt][nt][1]);
            }
            if (r0 + 8 < NROWS) {
                *(float2*)(y + (size_t)(r0 + 8) * PDOUT + col) =
                    make_float2(acc[mt][nt][2], acc[mt][nt][3]);
                *(__half2*)(yh + (size_t)(r0 + 8) * PDOUT + col) =
                    __floats2half2_rn(acc[mt][nt][2], acc[mt][nt][3]);
            }
        }
    }
}

// ---------------------------------------------------------------------------
// Fused scan + fill: 128 blocks x 256 threads, two software grid barriers.
// ---------------------------------------------------------------------------
#define SCAN_BLOCKS 128

__device__ __forceinline__ void grid_barrier(unsigned target, int tid) {
    __threadfence();
    __syncthreads();
    if (tid == 0) {
        atomicAdd(&g_bar, 1u);
        while (*(volatile unsigned*)&g_bar < target) { }
    }
    __syncthreads();
    __threadfence();
}

__global__ __launch_bounds__(256) void scanfill_kernel(
    const int* __restrict__ edge, const float* __restrict__ A)
{
    const int tid = threadIdx.x, b = blockIdx.x;
    const int lane = tid & 31, wid = tid >> 5;
    const int idx = b * 256 + tid;

    // ---- Phase 1: block scan ----
    const int v = (idx < PT) ? g_counts[idx] : 0;
    int inc = v;
#pragma unroll
    for (int d = 1; d < 32; d <<= 1) {
        int n = __shfl_up_sync(0xffffffffu, inc, d);
        if (lane >= d) inc += n;
    }
    __shared__ int ws[8], wexcl[8];
    if (lane == 31) ws[wid] = inc;
    __syncthreads();
    if (tid == 0) {
        int s = 0;
#pragma unroll
        for (int i = 0; i < 8; i++) { wexcl[i] = s; s += ws[i]; }
        g_bagg[b] = s;
    }
    __syncthreads();
    const int excl = wexcl[wid] + (inc - v);

    grid_barrier(SCAN_BLOCKS, tid);

    // ---- Phase 2: global offsets ----
    __shared__ int boff_s;
    if (tid == 0) {
        int s = 0;
#pragma unroll 8
        for (int i = 0; i < b; i++) s += g_bagg[i];
        boff_s = s;
    }
    __syncthreads();
    const int off = boff_s + excl;
    if (idx < PT) { g_offsets[idx] = off; g_cursor[idx] = off; }
    if (b == SCAN_BLOCKS - 1 && tid == 255) g_offsets[PT] = off + v;  // == PM

    grid_barrier(2 * SCAN_BLOCKS, tid);

    // ---- Phase 3: fill flattened payload + re-zero counts ----
    for (int m = idx; m < PM; m += SCAN_BLOCKS * 256) {
        const int   ni = edge[m];
        const int   no = edge[PM + m];
        const float w0 = A[m];
        const float w1 = A[PM + m];
        int pos = atomicAdd(&g_cursor[ni], 1);
        g_edata[pos] = make_float4(__int_as_float(no), w0, w1, 0.f);
    }
    for (int i = idx; i < PT; i += SCAN_BLOCKS * 256) g_counts[i] = 0;
}

// ---------------------------------------------------------------------------
// Gather-reduce: one warp per node t, all 4 (b,c) rows at once.
// Messages read from fp16 yh (half the L2 bytes); base + output in f32.
// ---------------------------------------------------------------------------
__global__ __launch_bounds__(256) void gather_kernel(
    const float* __restrict__ bias,
    const float* __restrict__ y,
    const __half* __restrict__ yh,
    float*       __restrict__ out)
{
    const unsigned t = blockIdx.x * 8u + (threadIdx.x >> 5);   // 0..PT-1 exact
    const int lane = threadIdx.x & 31;
    const int col = lane * 4;

    const float4 b4 = ((const float4*)bias)[lane];

    const size_t r00 = ((size_t)(t << 1)) << 7;            // b0 (c0 base)
    const size_t r10 = ((size_t)((PT + t) << 1)) << 7;     // b1

    float4 a00 = ((const float4*)(y + r00))[lane];
    float4 a01 = ((const float4*)(y + r00 + 128))[lane];
    float4 a10 = ((const float4*)(y + r10))[lane];
    float4 a11 = ((const float4*)(y + r10 + 128))[lane];
    a00.x += b4.x; a00.y += b4.y; a00.z += b4.z; a00.w += b4.w;
    a01.x += b4.x; a01.y += b4.y; a01.z += b4.z; a01.w += b4.w;
    a10.x += b4.x; a10.y += b4.y; a10.z += b4.z; a10.w += b4.w;
    a11.x += b4.x; a11.y += b4.y; a11.z += b4.z; a11.w += b4.w;

    const int s = g_offsets[t];
    const int e = g_offsets[t + 1];
    int p = s;

    for (; p + 2 <= e; p += 2) {
        const float4 e0 = __ldg(&g_edata[p]);
        const float4 e1 = __ldg(&g_edata[p + 1]);
        const unsigned n0 = (unsigned)__float_as_int(e0.x);
        const unsigned n1 = (unsigned)__float_as_int(e1.x);

        const size_t s0 = ((size_t)(n0 << 1)) << 7;
        const size_t t0 = ((size_t)((PT + n0) << 1)) << 7;
        const size_t s1 = ((size_t)(n1 << 1)) << 7;
        const size_t t1 = ((size_t)((PT + n1) << 1)) << 7;

        const float4 v00a = ld_half4(yh + s0 + col);
        const float4 v01a = ld_half4(yh + s0 + 128 + col);
        const float4 v10a = ld_half4(yh + t0 + col);
        const float4 v11a = ld_half4(yh + t0 + 128 + col);
        const float4 v00b = ld_half4(yh + s1 + col);
        const float4 v01b = ld_half4(yh + s1 + 128 + col);
        const float4 v10b = ld_half4(yh + t1 + col);
        const float4 v11b = ld_half4(yh + t1 + 128 + col);

        a00.x += e0.y * v00a.x; a00.y += e0.y * v00a.y; a00.z += e0.y * v00a.z; a00.w += e0.y * v00a.w;
        a01.x += e0.y * v01a.x; a01.y += e0.y * v01a.y; a01.z += e0.y * v01a.z; a01.w += e0.y * v01a.w;
        a10.x += e0.z * v10a.x; a10.y += e0.z * v10a.y; a10.z += e0.z * v10a.z; a10.w += e0.z * v10a.w;
        a11.x += e0.z * v11a.x; a11.y += e0.z * v11a.y; a11.z += e0.z * v11a.z; a11.w += e0.z * v11a.w;

        a00.x += e1.y * v00b.x; a00.y += e1.y * v00b.y; a00.z += e1.y * v00b.z; a00.w += e1.y * v00b.w;
        a01.x += e1.y * v01b.x; a01.y += e1.y * v01b.y; a01.z += e1.y * v01b.z; a01.w += e1.y * v01b.w;
        a10.x += e1.z * v10b.x; a10.y += e1.z * v10b.y; a10.z += e1.z * v10b.z; a10.w += e1.z * v10b.w;
        a11.x += e1.z * v11b.x; a11.y += e1.z * v11b.y; a11.z += e1.z * v11b.z; a11.w += e1.z * v11b.w;
    }
    if (p < e) {
        const float4 e0 = __ldg(&g_edata[p]);
        const unsigned n0 = (unsigned)__float_as_int(e0.x);
        const size_t s0 = ((size_t)(n0 << 1)) << 7;
        const size_t t0 = ((size_t)((PT + n0) << 1)) << 7;
        const float4 v00 = ld_half4(yh + s0 + col);
        const float4 v01 = ld_half4(yh + s0 + 128 + col);
        const float4 v10 = ld_half4(yh + t0 + col);
        const float4 v11 = ld_half4(yh + t0 + 128 + col);
        a00.x += e0.y * v00.x; a00.y += e0.y * v00.y; a00.z += e0.y * v00.z; a00.w += e0.y * v00.w;
        a01.x += e0.y * v01.x; a01.y += e0.y * v01.y; a01.z += e0.y * v01.z; a01.w += e0.y * v01.w;
        a10.x += e0.z * v10.x; a10.y += e0.z * v10.y; a10.z += e0.z * v10.z; a10.w += e0.z * v10.w;
        a11.x += e0.z * v11.x; a11.y += e0.z * v11.y; a11.z += e0.z * v11.z; a11.w += e0.z * v11.w;
    }

    ((float4*)(out + r00))[lane]       = a00;
    ((float4*)(out + r00 + 128))[lane] = a01;
    ((float4*)(out + r10))[lane]       = a10;
    ((float4*)(out + r10 + 128))[lane] = a11;
}

// ---------------------------------------------------------------------------
// Launch. Inputs: [0] x_1st, [1] x_2nd (unused), [2] edge, [3] A_masked,
//                 [4] W, [5] b
// ---------------------------------------------------------------------------
extern "C" void kernel_launch(void* const* d_in, const int* in_sizes, int n_in,
                              void* d_out, int out_size)
{
    const float* x1   = (const float*)d_in[0];
    const int*   edge = (const int*)  d_in[2];
    const float* A    = (const float*)d_in[3];
    const float* W    = (const float*)d_in[4];
    const float* bias = (const float*)d_in[5];
    float*       out  = (float*)d_out;

    float*  y  = nullptr; cudaGetSymbolAddress((void**)&y,  g_y);
    __half* yh = nullptr; cudaGetSymbolAddress((void**)&yh, g_yh);

    prep_kernel<<<64 + (PM + 255) / 256, 256>>>(W, edge);

    cudaFuncSetAttribute(mma_gemm_kernel,
                         cudaFuncAttributeMaxDynamicSharedMemorySize, GEMM_SMEM);
    mma_gemm_kernel<<<(NROWS + 127) / 128, 256, GEMM_SMEM>>>(x1, y, yh);

    scanfill_kernel<<<SCAN_BLOCKS, 256>>>(edge, A);

    gather_kernel<<<PT / 8, 256>>>(bias, y, yh, out);
}

// round 17
// speedup vs baseline: 1.0789x; 1.0789x over previous
#include <cuda_runtime.h>
#include <cuda_bf16.h>
#include <cuda_fp16.h>
#include <cstdint>

#define PB    2
#define PT    10000
#define PM    100000
#define PD    128
#define PDOUT 128
#define NROWS (PB * PT * 2)   // 40000

#define WPAD 136              // padded row length (bf16) -> 272 B rows, conflict-free ldmatrix

// ---------------------------------------------------------------------------
// Device scratch (no allocation allowed; zero-initialized at module load)
// ---------------------------------------------------------------------------
__device__ __align__(16) __half g_yh[NROWS * PDOUT];         // fp16 y = x@W^T (sole image)
__device__ __align__(16) __nv_bfloat16 g_Whi[PDOUT * WPAD];
__device__ __align__(16) __nv_bfloat16 g_Wlo[PDOUT * WPAD];
__device__ int g_counts[PT];        // zeroed at load; re-zeroed by scanfill each run
__device__ int g_offsets[PT + 1];
__device__ int g_cursor[PT];
__device__ __align__(16) float4 g_edata[PM];   // {bits(node_out), w_b0, w_b1, 0}
__device__ int g_bagg[128];
__device__ unsigned g_bar;          // grid-barrier counter, reset by prep each replay

// ---------------------------------------------------------------------------
// Warp MMA helpers (sm_80-baseline; valid in family-generic compute_103 PTX)
// ---------------------------------------------------------------------------
__device__ __forceinline__ uint32_t smem_u32(const void* p) {
    uint32_t a;
    asm("{ .reg .u64 t; cvta.to.shared.u64 t, %1; cvt.u32.u64 %0, t; }" : "=r"(a) : "l"(p));
    return a;
}
__device__ __forceinline__ void ldsm_x4(uint32_t* r, uint32_t addr) {
    asm volatile("ldmatrix.sync.aligned.m8n8.x4.shared.b16 {%0,%1,%2,%3}, [%4];"
                 : "=r"(r[0]), "=r"(r[1]), "=r"(r[2]), "=r"(r[3]) : "r"(addr));
}
__device__ __forceinline__ void ldsm_x2(uint32_t* r, uint32_t addr) {
    asm volatile("ldmatrix.sync.aligned.m8n8.x2.shared.b16 {%0,%1}, [%2];"
                 : "=r"(r[0]), "=r"(r[1]) : "r"(addr));
}
__device__ __forceinline__ void mma_bf16(float* c, const uint32_t* a, const uint32_t* b) {
    asm volatile("mma.sync.aligned.m16n8k16.row.col.f32.bf16.bf16.f32 "
                 "{%0,%1,%2,%3}, {%4,%5,%6,%7}, {%8,%9}, {%0,%1,%2,%3};"
                 : "+f"(c[0]), "+f"(c[1]), "+f"(c[2]), "+f"(c[3])
                 : "r"(a[0]), "r"(a[1]), "r"(a[2]), "r"(a[3]), "r"(b[0]), "r"(b[1]));
}
// 8 halfs (one uint4) -> 8 floats, FMA-accumulate with weight w
__device__ __forceinline__ void acc_half8(float* acc, uint4 v, float w) {
    const __half2* h = (const __half2*)&v;
#pragma unroll
    for (int i = 0; i < 4; i++) {
        const float2 f = __half22float2(h[i]);
        acc[2 * i]     += w * f.x;
        acc[2 * i + 1] += w * f.y;
    }
}

// ---------------------------------------------------------------------------
// Prep (fused): blocks 0..63 split W into bf16 hi/lo images;
// blocks 64.. histogram node_in. Resets the grid-barrier counter.
// ---------------------------------------------------------------------------
__global__ __launch_bounds__(256) void prep_kernel(
    const float* __restrict__ W, const int* __restrict__ edge)
{
    const int bid = blockIdx.x, tid = threadIdx.x;
    if (bid == 0 && tid == 0) g_bar = 0u;
    if (bid < 64) {
        int idx = bid * 256 + tid;                 // < 16384
        int o = idx >> 7, d = idx & 127;
        float w = W[idx];
        __nv_bfloat16 hi = __float2bfloat16(w);
        __nv_bfloat16 lo = __float2bfloat16(w - __bfloat162float(hi));
        g_Whi[o * WPAD + d] = hi;
        g_Wlo[o * WPAD + d] = lo;
    } else {
        int m = (bid - 64) * 256 + tid;
        if (m < PM) atomicAdd(&g_counts[edge[m]], 1);
    }
}

// ---------------------------------------------------------------------------
// GEMM: y = x @ W^T via mma.sync bf16 split (hi*hi + hi*lo + lo*hi).
// Epilogue writes ONLY the fp16 image g_yh (10.24 MB).
// ---------------------------------------------------------------------------
#define SM_XHI 0
#define SM_XLO 34816          // 128*272
#define SM_WHI 69632
#define SM_WLO 104448
#define GEMM_SMEM 139264

__global__ __launch_bounds__(256, 1) void mma_gemm_kernel(
    const float* __restrict__ x, __half* __restrict__ yh)
{
    extern __shared__ char smem[];
    const uint32_t sb = smem_u32(smem);
    const int tid = threadIdx.x, wid = tid >> 5, lane = tid & 31;
    const int row0 = blockIdx.x * 128;

    {
        const uint4* shi = (const uint4*)g_Whi;
        const uint4* slo = (const uint4*)g_Wlo;
        uint4* dhi = (uint4*)(smem + SM_WHI);
        uint4* dlo = (uint4*)(smem + SM_WLO);
#pragma unroll
        for (int i = tid; i < 2176; i += 256) { dhi[i] = shi[i]; dlo[i] = slo[i]; }
    }
    {
#pragma unroll
        for (int i = 0; i < 16; i++) {
            const int idx = i * 256 + tid;
            const int r = idx >> 5, q = idx & 31;
            const int grow = row0 + r;
            float4 v = make_float4(0.f, 0.f, 0.f, 0.f);
            if (grow < NROWS) v = *(const float4*)(x + (size_t)grow * PD + q * 4);

            __nv_bfloat162 h01 = __float22bfloat162_rn(make_float2(v.x, v.y));
            __nv_bfloat162 h23 = __float22bfloat162_rn(make_float2(v.z, v.w));
            float2 f01 = __bfloat1622float2(h01);
            float2 f23 = __bfloat1622float2(h23);
            __nv_bfloat162 l01 = __float22bfloat162_rn(make_float2(v.x - f01.x, v.y - f01.y));
            __nv_bfloat162 l23 = __float22bfloat162_rn(make_float2(v.z - f23.x, v.w - f23.y));

            const int boff = r * 272 + q * 8;
            *(uint2*)(smem + SM_XHI + boff) = make_uint2(*(uint32_t*)&h01, *(uint32_t*)&h23);
            *(uint2*)(smem + SM_XLO + boff) = make_uint2(*(uint32_t*)&l01, *(uint32_t*)&l23);
        }
    }
    __syncthreads();

    const int wm = wid & 1, wn = wid >> 1;
    const int m_base = wm * 64, n_base = wn * 32;

    float acc[4][4][4];
#pragma unroll
    for (int mt = 0; mt < 4; mt++)
#pragma unroll
        for (int nt = 0; nt < 4; nt++)
#pragma unroll
            for (int j = 0; j < 4; j++) acc[mt][nt][j] = 0.f;

    const int g  = lane >> 3;
    const int lr = lane & 7;

#pragma unroll
    for (int ks = 0; ks < 8; ks++) {
        const int k0 = ks * 16;
        uint32_t bh[4][2], bl[4][2];
#pragma unroll
        for (int nt = 0; nt < 4; nt++) {
            const int nrow = n_base + nt * 8 + lr;
            const int ncol = k0 + ((lane >> 3) & 1) * 8;
            const uint32_t off = (uint32_t)(nrow * 272 + ncol * 2);
            ldsm_x2(bh[nt], sb + SM_WHI + off);
            ldsm_x2(bl[nt], sb + SM_WLO + off);
        }
#pragma unroll
        for (int mt = 0; mt < 4; mt++) {
            const int arow = m_base + mt * 16 + (g & 1) * 8 + lr;
            const int acol = k0 + (g >> 1) * 8;
            const uint32_t off = (uint32_t)(arow * 272 + acol * 2);
            uint32_t ah[4], al[4];
            ldsm_x4(ah, sb + SM_XHI + off);
            ldsm_x4(al, sb + SM_XLO + off);
#pragma unroll
            for (int nt = 0; nt < 4; nt++) {
                mma_bf16(acc[mt][nt], ah, bh[nt]);
                mma_bf16(acc[mt][nt], ah, bl[nt]);
                mma_bf16(acc[mt][nt], al, bh[nt]);
            }
        }
    }

    const int erow = m_base + (lane >> 2);
    const int ecol = (lane & 3) * 2;
#pragma unroll
    for (int mt = 0; mt < 4; mt++) {
        const int r0 = row0 + erow + mt * 16;
#pragma unroll
        for (int nt = 0; nt < 4; nt++) {
            const int col = n_base + nt * 8 + ecol;
            if (r0 < NROWS)
                *(__half2*)(yh + (size_t)r0 * PDOUT + col) =
                    __floats2half2_rn(acc[mt][nt][0], acc[mt][nt][1]);
            if (r0 + 8 < NROWS)
                *(__half2*)(yh + (size_t)(r0 + 8) * PDOUT + col) =
                    __floats2half2_rn(acc[mt][nt][2], acc[mt][nt][3]);
        }
    }
}

// ---------------------------------------------------------------------------
// Fused scan + fill: 128 blocks x 256 threads, two software grid barriers.
// ---------------------------------------------------------------------------
#define SCAN_BLOCKS 128

__device__ __forceinline__ void grid_barrier(unsigned target, int tid) {
    __threadfence();
    __syncthreads();
    if (tid == 0) {
        atomicAdd(&g_bar, 1u);
        while (*(volatile unsigned*)&g_bar < target) { }
    }
    __syncthreads();
    __threadfence();
}

__global__ __launch_bounds__(256) void scanfill_kernel(
    const int* __restrict__ edge, const float* __restrict__ A)
{
    const int tid = threadIdx.x, b = blockIdx.x;
    const int lane = tid & 31, wid = tid >> 5;
    const int idx = b * 256 + tid;

    // ---- Phase 1: block scan ----
    const int v = (idx < PT) ? g_counts[idx] : 0;
    int inc = v;
#pragma unroll
    for (int d = 1; d < 32; d <<= 1) {
        int n = __shfl_up_sync(0xffffffffu, inc, d);
        if (lane >= d) inc += n;
    }
    __shared__ int ws[8], wexcl[8];
    if (lane == 31) ws[wid] = inc;
    __syncthreads();
    if (tid == 0) {
        int s = 0;
#pragma unroll
        for (int i = 0; i < 8; i++) { wexcl[i] = s; s += ws[i]; }
        g_bagg[b] = s;
    }
    __syncthreads();
    const int excl = wexcl[wid] + (inc - v);

    grid_barrier(SCAN_BLOCKS, tid);

    // ---- Phase 2: global offsets ----
    __shared__ int boff_s;
    if (tid == 0) {
        int s = 0;
#pragma unroll 8
        for (int i = 0; i < b; i++) s += g_bagg[i];
        boff_s = s;
    }
    __syncthreads();
    const int off = boff_s + excl;
    if (idx < PT) { g_offsets[idx] = off; g_cursor[idx] = off; }
    if (b == SCAN_BLOCKS - 1 && tid == 255) g_offsets[PT] = off + v;  // == PM

    grid_barrier(2 * SCAN_BLOCKS, tid);

    // ---- Phase 3: fill flattened payload + re-zero counts ----
    for (int m = idx; m < PM; m += SCAN_BLOCKS * 256) {
        const int   ni = edge[m];
        const int   no = edge[PM + m];
        const float w0 = A[m];
        const float w1 = A[PM + m];
        int pos = atomicAdd(&g_cursor[ni], 1);
        g_edata[pos] = make_float4(__int_as_float(no), w0, w1, 0.f);
    }
    for (int i = idx; i < PT; i += SCAN_BLOCKS * 256) g_counts[i] = 0;
}

// ---------------------------------------------------------------------------
// Gather-reduce: one warp per (node, batch) pair -> 20,000 warps.
// In fp16 the (c0, c1) rows of a pair are 512 B contiguous, so ONE
// uint4-per-lane warp load covers both rows of one message. 4-edge unroll.
// Lane l: c = l>>4, features [(l&15)*8, (l&15)*8+8).
// ---------------------------------------------------------------------------
__global__ __launch_bounds__(256) void gather_kernel(
    const float* __restrict__ bias,
    const __half* __restrict__ yh,
    float*       __restrict__ out)
{
    const unsigned wu = blockIdx.x * 8u + (threadIdx.x >> 5);  // 0..19999 exact
    const int lane = threadIdx.x & 31;
    const unsigned b = wu & 1;        // b0/b1 warps of a node adjacent (share edata via L1)
    const unsigned t = wu >> 1;

    // Pair base (256 elements per (t,b) pair, same linear index for yh & out)
    const size_t pair = ((size_t)(b * PT + t)) << 8;
    const int lo = lane * 8;                       // element offset of this lane's 8-chunk

    // Base value from fp16 image + bias
    float acc[8];
    {
        const uint4 v = *(const uint4*)(yh + pair + lo);
        const __half2* h = (const __half2*)&v;
        const int bcol = (lane & 15) * 8;
        const float4 bA = *(const float4*)(bias + bcol);
        const float4 bB = *(const float4*)(bias + bcol + 4);
        const float2 f0 = __half22float2(h[0]);
        const float2 f1 = __half22float2(h[1]);
        const float2 f2 = __half22float2(h[2]);
        const float2 f3 = __half22float2(h[3]);
        acc[0] = f0.x + bA.x; acc[1] = f0.y + bA.y;
        acc[2] = f1.x + bA.z; acc[3] = f1.y + bA.w;
        acc[4] = f2.x + bB.x; acc[5] = f2.y + bB.y;
        acc[6] = f3.x + bB.z; acc[7] = f3.y + bB.w;
    }

    const int s = g_offsets[t];
    const int e = g_offsets[t + 1];
    int p = s;

    for (; p + 4 <= e; p += 4) {
        const float4 e0 = __ldg(&g_edata[p]);
        const float4 e1 = __ldg(&g_edata[p + 1]);
        const float4 e2 = __ldg(&g_edata[p + 2]);
        const float4 e3 = __ldg(&g_edata[p + 3]);
        const float w0 = b ? e0.z : e0.y;
        const float w1 = b ? e1.z : e1.y;
        const float w2 = b ? e2.z : e2.y;
        const float w3 = b ? e3.z : e3.y;
        const size_t p0 = ((size_t)(b * PT + (unsigned)__float_as_int(e0.x))) << 8;
        const size_t p1 = ((size_t)(b * PT + (unsigned)__float_as_int(e1.x))) << 8;
        const size_t p2 = ((size_t)(b * PT + (unsigned)__float_as_int(e2.x))) << 8;
        const size_t p3 = ((size_t)(b * PT + (unsigned)__float_as_int(e3.x))) << 8;

        const uint4 v0 = *(const uint4*)(yh + p0 + lo);
        const uint4 v1 = *(const uint4*)(yh + p1 + lo);
        const uint4 v2 = *(const uint4*)(yh + p2 + lo);
        const uint4 v3 = *(const uint4*)(yh + p3 + lo);

        acc_half8(acc, v0, w0);
        acc_half8(acc, v1, w1);
        acc_half8(acc, v2, w2);
        acc_half8(acc, v3, w3);
    }
    for (; p < e; p++) {
        const float4 e0 = __ldg(&g_edata[p]);
        const float w0 = b ? e0.z : e0.y;
        const size_t p0 = ((size_t)(b * PT + (unsigned)__float_as_int(e0.x))) << 8;
        const uint4 v0 = *(const uint4*)(yh + p0 + lo);
        acc_half8(acc, v0, w0);
    }

    float* dst = out + pair + lo;
    *(float4*)(dst)     = make_float4(acc[0], acc[1], acc[2], acc[3]);
    *(float4*)(dst + 4) = make_float4(acc[4], acc[5], acc[6], acc[7]);
}

// ---------------------------------------------------------------------------
// Launch. Inputs: [0] x_1st, [1] x_2nd (unused), [2] edge, [3] A_masked,
//                 [4] W, [5] b
// ---------------------------------------------------------------------------
extern "C" void kernel_launch(void* const* d_in, const int* in_sizes, int n_in,
                              void* d_out, int out_size)
{
    const float* x1   = (const float*)d_in[0];
    const int*   edge = (const int*)  d_in[2];
    const float* A    = (const float*)d_in[3];
    const float* W    = (const float*)d_in[4];
    const float* bias = (const float*)d_in[5];
    float*       out  = (float*)d_out;

    __half* yh = nullptr; cudaGetSymbolAddress((void**)&yh, g_yh);

    prep_kernel<<<64 + (PM + 255) / 256, 256>>>(W, edge);

    cudaFuncSetAttribute(mma_gemm_kernel,
                         cudaFuncAttributeMaxDynamicSharedMemorySize, GEMM_SMEM);
    mma_gemm_kernel<<<(NROWS + 127) / 128, 256, GEMM_SMEM>>>(x1, yh);

    scanfill_kernel<<<SCAN_BLOCKS, 256>>>(edge, A);

    gather_kernel<<<(PB * PT) / 8, 256>>>(bias, yh, out);
}